// round 5
// baseline (speedup 1.0000x reference)
#include <cuda_runtime.h>
#include <cuda_bf16.h>
#include <math.h>
#include <cstdint>

// ---------------- problem constants ----------------
#define NNODES 8192
#define NEDGES 65536
#define DIN    768
#define DHID   768
#define H1N    8
#define H2N    1
#define NEG_SLOPE 0.2f
#define EPSV 1e-16f

// ---------------- scratch (device globals; no allocs allowed) ----------------
__device__ float g_h1[(size_t)NNODES * (H1N * DHID)];   // layer-1 GEMM out [8192, 6144]
__device__ float g_o1[(size_t)NNODES * (H1N * DHID)];   // elu(agg1 + b1)   [8192, 6144]
__device__ float g_h2[(size_t)NNODES * DHID];           // layer-2 GEMM out [8192, 768]
__device__ float g_w1t[(size_t)(H1N * DHID) * DIN];     // W1^T fp32 [6144, 768]
__device__ float g_w2t[(size_t)DHID * (H1N * DHID)];    // W2^T fp32 [768, 6144]

// int8 two-digit quantized operands
__device__ __align__(16) char g_aq1[(size_t)NNODES * (H1N * DHID)];  // A digit1 (max K=6144)
__device__ __align__(16) char g_aq2[(size_t)NNODES * (H1N * DHID)];  // A digit2
__device__ __align__(16) char g_wq1a[(size_t)(H1N * DHID) * DIN];    // W1^T digit1 [6144,768]
__device__ __align__(16) char g_wq1b[(size_t)(H1N * DHID) * DIN];
__device__ __align__(16) char g_wq2a[(size_t)DHID * (H1N * DHID)];   // W2^T digit1 [768,6144]
__device__ __align__(16) char g_wq2b[(size_t)DHID * (H1N * DHID)];
__device__ float g_sa [NNODES];          // A row scales
__device__ float g_sw1[H1N * DHID];      // W1^T row scales (= W1 col scales)
__device__ float g_sw2[DHID];            // W2^T row scales

__device__ float g_as1[NNODES * H1N];
__device__ float g_ad1[NNODES * H1N];
__device__ float g_as2[NNODES * H2N];
__device__ float g_ad2[NNODES * H2N];
__device__ float g_alpha1[(size_t)NEDGES * H1N];
__device__ float g_alpha2[(size_t)NEDGES * H2N];
__device__ int   g_deg[NNODES];
__device__ int   g_cur[NNODES];
__device__ int   g_off[NNODES + 1];
__device__ int   g_eid[NEDGES];

// ---------------- small helpers ----------------
__device__ __forceinline__ void cp16(unsigned dst, const void* src) {
    asm volatile("cp.async.cg.shared.global [%0], [%1], 16;" :: "r"(dst), "l"(src));
}
__device__ __forceinline__ uint32_t smem_u32(const void* p) {
    return (uint32_t)__cvta_generic_to_shared(p);
}

#define MMA_S8(d, a, b)                                                                \
    asm volatile(                                                                      \
        "mma.sync.aligned.m16n8k32.row.col.s32.s8.s8.s32 "                             \
        "{%0,%1,%2,%3},{%4,%5,%6,%7},{%8,%9},{%0,%1,%2,%3};"                           \
        : "+r"((d)[0]), "+r"((d)[1]), "+r"((d)[2]), "+r"((d)[3])                       \
        : "r"((a)[0]), "r"((a)[1]), "r"((a)[2]), "r"((a)[3]), "r"((b)[0]), "r"((b)[1]))

#define LDSM_X4(r, addr)                                                               \
    asm volatile("ldmatrix.sync.aligned.m8n8.x4.shared.b16 {%0,%1,%2,%3}, [%4];"       \
        : "=r"((r)[0]), "=r"((r)[1]), "=r"((r)[2]), "=r"((r)[3]) : "r"(addr))

#define LDSM_X2(r, addr)                                                               \
    asm volatile("ldmatrix.sync.aligned.m8n8.x2.shared.b16 {%0,%1}, [%2];"             \
        : "=r"((r)[0]), "=r"((r)[1]) : "r"(addr))

// ---------------- quantize rows: A[M,K] fp32 -> q1,q2 int8 + per-row scale ----------------
// v = s * (128*q1 + q2), s = rowmax/16256, q1 in [-127,127], q2 in [-64,64].
__global__ void __launch_bounds__(256)
quant_rows(const float* __restrict__ A, char* __restrict__ q1, char* __restrict__ q2,
           float* __restrict__ s, int K)
{
    int row = blockIdx.x;
    int tid = threadIdx.x, lane = tid & 31, wid = tid >> 5;
    const float4* ap = (const float4*)(A + (size_t)row * K);
    int k4 = K >> 2;

    float m = 0.f;
    for (int i = tid; i < k4; i += 256) {
        float4 v = ap[i];
        m = fmaxf(m, fmaxf(fmaxf(fabsf(v.x), fabsf(v.y)), fmaxf(fabsf(v.z), fabsf(v.w))));
    }
#pragma unroll
    for (int o = 16; o; o >>= 1) m = fmaxf(m, __shfl_xor_sync(0xffffffffu, m, o));
    __shared__ float wred[8];
    __shared__ float s_inv;
    if (lane == 0) wred[wid] = m;
    __syncthreads();
    if (tid == 0) {
        float mx = wred[0];
#pragma unroll
        for (int i = 1; i < 8; i++) mx = fmaxf(mx, wred[i]);
        s[row] = mx * (1.f / 16256.f);
        s_inv = (mx > 0.f) ? (16256.f / mx) : 0.f;
    }
    __syncthreads();
    float inv = s_inv;

    char4* q1p = (char4*)(q1 + (size_t)row * K);
    char4* q2p = (char4*)(q2 + (size_t)row * K);
    for (int i = tid; i < k4; i += 256) {
        float4 v = ap[i];
        char4 c1, c2;
        {
            float t = v.x * inv; int a = __float2int_rn(t * 0.0078125f);
            int b = __float2int_rn(t - 128.f * a); c1.x = (char)a; c2.x = (char)b;
        }
        {
            float t = v.y * inv; int a = __float2int_rn(t * 0.0078125f);
            int b = __float2int_rn(t - 128.f * a); c1.y = (char)a; c2.y = (char)b;
        }
        {
            float t = v.z * inv; int a = __float2int_rn(t * 0.0078125f);
            int b = __float2int_rn(t - 128.f * a); c1.z = (char)a; c2.z = (char)b;
        }
        {
            float t = v.w * inv; int a = __float2int_rn(t * 0.0078125f);
            int b = __float2int_rn(t - 128.f * a); c1.w = (char)a; c2.w = (char)b;
        }
        q1p[i] = c1; q2p[i] = c2;
    }
}

// ---------------- plain transpose: in [R,C] -> out [C,R] ----------------
__global__ void transpose_kernel(const float* __restrict__ in, float* __restrict__ out,
                                 int R, int C)
{
    __shared__ float t[32][33];
    int bx = blockIdx.x * 32, by = blockIdx.y * 32;
#pragma unroll
    for (int i = 0; i < 4; i++)
        t[threadIdx.y + 8 * i][threadIdx.x] =
            in[(size_t)(by + threadIdx.y + 8 * i) * C + bx + threadIdx.x];
    __syncthreads();
#pragma unroll
    for (int i = 0; i < 4; i++)
        out[(size_t)(bx + threadIdx.y + 8 * i) * R + by + threadIdx.x] =
            t[threadIdx.x][threadIdx.y + 8 * i];
}

// ---------------- CSR build ----------------
__global__ void zero_counts_kernel() {
    int i = blockIdx.x * blockDim.x + threadIdx.x;
    if (i < NNODES) { g_deg[i] = 0; g_cur[i] = 0; }
}
__global__ void count_kernel(const int* __restrict__ dst) {
    int e = blockIdx.x * blockDim.x + threadIdx.x;
    if (e < NEDGES) atomicAdd(&g_deg[dst[e]], 1);
}
__global__ void scan_kernel() {
    __shared__ int s[1024];
    int t = threadIdx.x;
    int base = t * 8;
    int local[8];
    int run = 0;
#pragma unroll
    for (int i = 0; i < 8; i++) { local[i] = run; run += g_deg[base + i]; }
    s[t] = run;
    __syncthreads();
    for (int o = 1; o < 1024; o <<= 1) {
        int v = (t >= o) ? s[t - o] : 0;
        __syncthreads();
        s[t] += v;
        __syncthreads();
    }
    int prev = (t == 0) ? 0 : s[t - 1];
#pragma unroll
    for (int i = 0; i < 8; i++) g_off[base + i] = prev + local[i];
    if (t == 1023) g_off[NNODES] = s[1023];
}
__global__ void scatter_kernel(const int* __restrict__ dst) {
    int e = blockIdx.x * blockDim.x + threadIdx.x;
    if (e < NEDGES) {
        int d = dst[e];
        int p = atomicAdd(&g_cur[d], 1);
        g_eid[g_off[d] + p] = e;
    }
}

// ---------------- fused two-digit int8 GEMM ----------------
// C[M,N] = sum_k A[m,k]*B[k,n] with A = sa_m*(128*A1 + A2), Bt = sb_n*(128*B1 + B2),
// Bt stored [N,K] row-major (K contiguous).
// C = sa*sb*(16384*P11 + 128*(P12 + P21));  P22 dropped (O(2^-30) relative).
// Block tile 128x128x64, 8 warps (2x4), warp tile 64x32, double-buffered cp.async,
// ldmatrix fragment loads with XOR-16B swizzle.
#define IG_STAGE 32768                 // A1 8K, A2 8K, B1 8K, B2 8K
#define IG_SMEM  (2 * IG_STAGE)

__global__ void __launch_bounds__(256, 1)
igemm(const char* __restrict__ A1, const char* __restrict__ A2,
      const char* __restrict__ B1, const char* __restrict__ B2,
      const float* __restrict__ sa, const float* __restrict__ sb,
      float* __restrict__ C, int K, int N)
{
    extern __shared__ char smem[];
    const uint32_t sbase = smem_u32(smem);
    const int tid = threadIdx.x, wid = tid >> 5, lane = tid & 31;
    const int bn = blockIdx.x, bm = blockIdx.y;
    const int wm = (wid >> 2) * 64;       // warp M origin
    const int wn = (wid & 3) * 32;        // warp N origin
    const int g = lane >> 2, tg = lane & 3;

    const char* Ag1 = A1 + (size_t)(bm * 128) * K;
    const char* Ag2 = A2 + (size_t)(bm * 128) * K;
    const char* Bg1 = B1 + (size_t)(bn * 128) * K;
    const char* Bg2 = B2 + (size_t)(bn * 128) * K;

    int acc1[4][4][4] = {};
    int accm[4][4][4] = {};

    const int T = K / 64;

    // chunk mapping for cp.async: 512 16B-chunks per 8KB tile, 2 per thread.
    // row r (0..127), chunk c (0..3): u = (4*(r&1)+c) ^ ((r>>1)&7); off = (r>>1)*128 + u*16
    auto load_tile = [&](int t) {
        int st = t & 1;
        uint32_t base = sbase + st * IG_STAGE;
        int k0 = t * 64;
#pragma unroll
        for (int i = 0; i < 2; i++) {
            int ci = tid + i * 256;
            int r = ci >> 2, c = ci & 3;
            uint32_t off = (uint32_t)((r >> 1) * 128 + (((4 * (r & 1) + c) ^ ((r >> 1) & 7)) * 16));
            const size_t go = (size_t)r * K + k0 + c * 16;
            cp16(base + off,              Ag1 + go);
            cp16(base + 8192 + off,       Ag2 + go);
            cp16(base + 16384 + off,      Bg1 + go);
            cp16(base + 24576 + off,      Bg2 + go);
        }
        asm volatile("cp.async.commit_group;");
    };

    load_tile(0);

    for (int t = 0; t < T; t++) {
        if (t + 1 < T) load_tile(t + 1);
        else asm volatile("cp.async.commit_group;");
        asm volatile("cp.async.wait_group 1;");
        __syncthreads();

        uint32_t base = sbase + (t & 1) * IG_STAGE;
#pragma unroll
        for (int kc = 0; kc < 2; kc++) {
            // fragment smem addresses (ldmatrix, same swizzle)
            uint32_t a1f[4][4], a2f[4][4], b1f[4][2], b2f[4][2];
#pragma unroll
            for (int mi = 0; mi < 4; mi++) {
                int r = wm + mi * 16 + (lane & 15);
                int cc = kc * 2 + (lane >> 4);
                uint32_t off = (uint32_t)((r >> 1) * 128 +
                               (((4 * (r & 1) + cc) ^ ((r >> 1) & 7)) * 16));
                LDSM_X4(a1f[mi], base + off);
                LDSM_X4(a2f[mi], base + 8192 + off);
            }
#pragma unroll
            for (int ni = 0; ni < 4; ni++) {
                int r = wn + ni * 8 + (lane & 7);
                int cc = kc * 2 + ((lane >> 3) & 1);
                uint32_t off = (uint32_t)((r >> 1) * 128 +
                               (((4 * (r & 1) + cc) ^ ((r >> 1) & 7)) * 16));
                LDSM_X2(b1f[ni], base + 16384 + off);
                LDSM_X2(b2f[ni], base + 24576 + off);
            }
#pragma unroll
            for (int mi = 0; mi < 4; mi++)
#pragma unroll
                for (int ni = 0; ni < 4; ni++) {
                    MMA_S8(acc1[mi][ni], a1f[mi], b1f[ni]);
                    MMA_S8(accm[mi][ni], a1f[mi], b2f[ni]);
                    MMA_S8(accm[mi][ni], a2f[mi], b1f[ni]);
                }
        }
        __syncthreads();
    }

    // epilogue: c = (16384*P11 + 128*Pmid) * sa_row * sb_col
#pragma unroll
    for (int mi = 0; mi < 4; mi++) {
        int r0 = bm * 128 + wm + mi * 16 + g;
        float sa0 = sa[r0], sa1 = sa[r0 + 8];
#pragma unroll
        for (int ni = 0; ni < 4; ni++) {
            int cb = bn * 128 + wn + ni * 8 + tg * 2;
            float sb0 = sb[cb], sb1 = sb[cb + 1];
            const int* p1 = acc1[mi][ni];
            const int* pm = accm[mi][ni];
            float v0 = (16384.f * __int2float_rn(p1[0]) + 128.f * __int2float_rn(pm[0])) * sa0 * sb0;
            float v1 = (16384.f * __int2float_rn(p1[1]) + 128.f * __int2float_rn(pm[1])) * sa0 * sb1;
            float v2 = (16384.f * __int2float_rn(p1[2]) + 128.f * __int2float_rn(pm[2])) * sa1 * sb0;
            float v3 = (16384.f * __int2float_rn(p1[3]) + 128.f * __int2float_rn(pm[3])) * sa1 * sb1;
            float* cp = C + (size_t)r0 * N + cb;
            *(float2*)cp = make_float2(v0, v1);
            *(float2*)(cp + (size_t)8 * N) = make_float2(v2, v3);
        }
    }
}

// ---------------- per-(node,head) attention coefficients ----------------
__global__ void alphas_kernel(const float* __restrict__ h,
                              const float* __restrict__ a_s, const float* __restrict__ a_d,
                              float* __restrict__ out_s, float* __restrict__ out_d,
                              int H, int C)
{
    int w = (blockIdx.x * blockDim.x + threadIdx.x) >> 5;
    int lane = threadIdx.x & 31;
    if (w >= NNODES * H) return;
    int n = w / H, hd = w % H;
    const float* hp  = h + (size_t)n * H * C + (size_t)hd * C;
    const float* asp = a_s + (size_t)hd * C;
    const float* adp = a_d + (size_t)hd * C;
    float ss = 0.f, sd = 0.f;
    for (int c = lane; c < C; c += 32) {
        float v = hp[c];
        ss += v * asp[c];
        sd += v * adp[c];
    }
#pragma unroll
    for (int o = 16; o; o >>= 1) {
        ss += __shfl_down_sync(0xffffffffu, ss, o);
        sd += __shfl_down_sync(0xffffffffu, sd, o);
    }
    if (lane == 0) { out_s[w] = ss; out_d[w] = sd; }
}

// ---------------- per-(dst,head) segment softmax ----------------
__global__ void softmax_kernel(const int* __restrict__ src,
                               const float* __restrict__ as, const float* __restrict__ ad,
                               float* __restrict__ alpha, int H)
{
    int idx = blockIdx.x * blockDim.x + threadIdx.x;
    if (idx >= NNODES * H) return;
    int d = idx / H, hd = idx % H;
    int s0 = g_off[d], s1 = g_off[d + 1];
    if (s0 == s1) return;
    float adv = ad[idx];

    float m = -1e30f;
    for (int i = s0; i < s1; i++) {
        int e = g_eid[i];
        float x = as[src[e] * H + hd] + adv;
        x = (x > 0.f) ? x : NEG_SLOPE * x;
        m = fmaxf(m, x);
    }
    float sum = 0.f;
    for (int i = s0; i < s1; i++) {
        int e = g_eid[i];
        float x = as[src[e] * H + hd] + adv;
        x = (x > 0.f) ? x : NEG_SLOPE * x;
        float w = __expf(x - m);
        alpha[(size_t)e * H + hd] = w;
        sum += w;
    }
    float inv = 1.f / (sum + EPSV);
    for (int i = s0; i < s1; i++) {
        int e = g_eid[i];
        alpha[(size_t)e * H + hd] *= inv;
    }
}

// ---------------- aggregation ----------------
__global__ void __launch_bounds__(192)
aggregate_kernel(const int* __restrict__ src, const float* __restrict__ alpha,
                 const float* __restrict__ h, float* __restrict__ out,
                 const float* __restrict__ bias, int H, int C, int do_elu)
{
    int d  = blockIdx.x / H;
    int hd = blockIdx.x % H;
    int t  = threadIdx.x;
    int s0 = g_off[d], s1 = g_off[d + 1];
    size_t rs = (size_t)H * C;

    float4 acc = make_float4(0.f, 0.f, 0.f, 0.f);
    for (int i = s0; i < s1; i++) {
        int e = g_eid[i];
        float a = alpha[(size_t)e * H + hd];
        float4 v = *(((const float4*)(h + (size_t)src[e] * rs + (size_t)hd * C)) + t);
        acc.x += a * v.x; acc.y += a * v.y; acc.z += a * v.z; acc.w += a * v.w;
    }
    float4 b = *(((const float4*)(bias + (size_t)hd * C)) + t);
    acc.x += b.x; acc.y += b.y; acc.z += b.z; acc.w += b.w;
    if (do_elu) {
        acc.x = (acc.x > 0.f) ? acc.x : expm1f(acc.x);
        acc.y = (acc.y > 0.f) ? acc.y : expm1f(acc.y);
        acc.z = (acc.z > 0.f) ? acc.z : expm1f(acc.z);
        acc.w = (acc.w > 0.f) ? acc.w : expm1f(acc.w);
    }
    *(((float4*)(out + (size_t)d * rs + (size_t)hd * C)) + t) = acc;
}

// ---------------- launch ----------------
extern "C" void kernel_launch(void* const* d_in, const int* in_sizes, int n_in,
                              void* d_out, int out_size)
{
    const float* x    = (const float*)d_in[0];
    const float* W1   = (const float*)d_in[1];
    const float* a_s1 = (const float*)d_in[2];
    const float* a_d1 = (const float*)d_in[3];
    const float* b1   = (const float*)d_in[4];
    const float* W2   = (const float*)d_in[5];
    const float* a_s2 = (const float*)d_in[6];
    const float* a_d2 = (const float*)d_in[7];
    const float* b2   = (const float*)d_in[8];
    const int* edges  = (const int*)d_in[9];
    const int* src = edges;
    const int* dst = edges + NEDGES;
    float* out = (float*)d_out;

    float *h1, *o1, *h2, *w1t, *w2t, *sa, *sw1, *sw2;
    float *as1, *ad1, *as2, *ad2, *al1, *al2;
    char *aq1, *aq2, *wq1a, *wq1b, *wq2a, *wq2b;
    cudaGetSymbolAddress((void**)&h1,  g_h1);
    cudaGetSymbolAddress((void**)&o1,  g_o1);
    cudaGetSymbolAddress((void**)&h2,  g_h2);
    cudaGetSymbolAddress((void**)&w1t, g_w1t);
    cudaGetSymbolAddress((void**)&w2t, g_w2t);
    cudaGetSymbolAddress((void**)&sa,  g_sa);
    cudaGetSymbolAddress((void**)&sw1, g_sw1);
    cudaGetSymbolAddress((void**)&sw2, g_sw2);
    cudaGetSymbolAddress((void**)&aq1, g_aq1);
    cudaGetSymbolAddress((void**)&aq2, g_aq2);
    cudaGetSymbolAddress((void**)&wq1a, g_wq1a);
    cudaGetSymbolAddress((void**)&wq1b, g_wq1b);
    cudaGetSymbolAddress((void**)&wq2a, g_wq2a);
    cudaGetSymbolAddress((void**)&wq2b, g_wq2b);
    cudaGetSymbolAddress((void**)&as1, g_as1);
    cudaGetSymbolAddress((void**)&ad1, g_ad1);
    cudaGetSymbolAddress((void**)&as2, g_as2);
    cudaGetSymbolAddress((void**)&ad2, g_ad2);
    cudaGetSymbolAddress((void**)&al1, g_alpha1);
    cudaGetSymbolAddress((void**)&al2, g_alpha2);

    cudaFuncSetAttribute(igemm, cudaFuncAttributeMaxDynamicSharedMemorySize, IG_SMEM);

    dim3 tblk(32, 8);

    // 1: quantize x  (A of gemm1, K=768)
    quant_rows<<<NNODES, 256>>>(x, aq1, aq2, sa, DIN);
    // 2: W1 [768,6144] -> W1^T [6144,768]
    {
        dim3 gt((H1N * DHID) / 32, DIN / 32);
        transpose_kernel<<<gt, tblk>>>(W1, w1t, DIN, H1N * DHID);
    }
    // 3: quantize W1^T rows (K=768)
    quant_rows<<<H1N * DHID, 256>>>(w1t, wq1a, wq1b, sw1, DIN);
    // 4: GEMM1  h1[8192,6144]  (ncu capture slot)
    {
        dim3 grid((H1N * DHID) / 128, NNODES / 128);   // (48, 64)
        igemm<<<grid, 256, IG_SMEM>>>(aq1, aq2, wq1a, wq1b, sa, sw1, h1, DIN, H1N * DHID);
    }
    // 5-6: W2 transpose + quantize (independent of gemm1)
    {
        dim3 gt(DHID / 32, (H1N * DHID) / 32);
        transpose_kernel<<<gt, tblk>>>(W2, w2t, H1N * DHID, DHID);
    }
    quant_rows<<<DHID, 256>>>(w2t, wq2a, wq2b, sw2, H1N * DHID);
    // 7-10: CSR build
    zero_counts_kernel<<<(NNODES + 255) / 256, 256>>>();
    count_kernel<<<(NEDGES + 255) / 256, 256>>>(dst);
    scan_kernel<<<1, 1024>>>();
    scatter_kernel<<<(NEDGES + 255) / 256, 256>>>(dst);
    // 11-13: layer-1 attention + aggregation
    alphas_kernel<<<(NNODES * H1N * 32 + 255) / 256, 256>>>(h1, a_s1, a_d1, as1, ad1, H1N, DHID);
    softmax_kernel<<<(NNODES * H1N + 255) / 256, 256>>>(src, as1, ad1, al1, H1N);
    aggregate_kernel<<<NNODES * H1N, DHID / 4>>>(src, al1, h1, o1, b1, H1N, DHID, 1);
    // 14: quantize o1 (A of gemm2, K=6144)
    quant_rows<<<NNODES, 256>>>(o1, aq1, aq2, sa, H1N * DHID);
    // 15: GEMM2  h2[8192,768]
    {
        dim3 grid((H2N * DHID) / 128, NNODES / 128);   // (6, 64)
        igemm<<<grid, 256, IG_SMEM>>>(aq1, aq2, wq2a, wq2b, sa, sw2, h2, H1N * DHID, H2N * DHID);
    }
    // 16-18: layer-2 attention + aggregation
    alphas_kernel<<<(NNODES * H2N * 32 + 255) / 256, 256>>>(h2, a_s2, a_d2, as2, ad2, H2N, DHID);
    softmax_kernel<<<(NNODES * H2N + 255) / 256, 256>>>(src, as2, ad2, al2, H2N);
    aggregate_kernel<<<NNODES * H2N, DHID / 4>>>(src, al2, h2, out, b2, H2N, DHID, 0);
}

// round 6
// speedup vs baseline: 3.7399x; 3.7399x over previous
#include <cuda_runtime.h>
#include <cuda_fp16.h>
#include <math.h>
#include <cstdint>

// ---------------- problem constants ----------------
#define NNODES 8192
#define NEDGES 65536
#define DIN    768
#define DHID   768
#define H1N    8
#define H2N    1
#define NEG_SLOPE 0.2f
#define EPSV 1e-16f

// ---------------- scratch (device globals; no allocs allowed) ----------------
__device__ float  g_h1[(size_t)NNODES * (H1N * DHID)];     // x @ W1        [8192, 6144] fp32
__device__ float  g_h2[(size_t)NNODES * DHID];             // o1 @ W2       [8192, 768]  fp32
__device__ __half g_xh [(size_t)NNODES * DIN];             // x fp16
__device__ __half g_o1h[(size_t)NNODES * (H1N * DHID)];    // elu(agg1+b1) fp16 (GEMM2 A)
__device__ __half g_w1th[(size_t)(H1N * DHID) * DIN];      // W1^T fp16 [6144, 768]
__device__ __half g_w2th[(size_t)DHID * (H1N * DHID)];     // W2^T fp16 [768, 6144]
__device__ float g_as1[NNODES * H1N];
__device__ float g_ad1[NNODES * H1N];
__device__ float g_as2[NNODES * H2N];
__device__ float g_ad2[NNODES * H2N];
__device__ float g_alpha1[(size_t)NEDGES * H1N];
__device__ float g_alpha2[(size_t)NEDGES * H2N];
__device__ int   g_deg[NNODES];
__device__ int   g_cur[NNODES];
__device__ int   g_off[NNODES + 1];
__device__ int   g_eid[NEDGES];

// ---------------- helpers ----------------
__device__ __forceinline__ void cp16(unsigned dst, const void* src) {
    asm volatile("cp.async.cg.shared.global [%0], [%1], 16;" :: "r"(dst), "l"(src));
}
__device__ __forceinline__ uint32_t smem_u32(const void* p) {
    return (uint32_t)__cvta_generic_to_shared(p);
}

#define MMA_F16(d, a, b)                                                               \
    asm volatile(                                                                      \
        "mma.sync.aligned.m16n8k16.row.col.f32.f16.f16.f32 "                           \
        "{%0,%1,%2,%3},{%4,%5,%6,%7},{%8,%9},{%0,%1,%2,%3};"                           \
        : "+f"((d)[0]), "+f"((d)[1]), "+f"((d)[2]), "+f"((d)[3])                       \
        : "r"((a)[0]), "r"((a)[1]), "r"((a)[2]), "r"((a)[3]), "r"((b)[0]), "r"((b)[1]))

// ---------------- fp32 -> fp16 convert ----------------
__global__ void f2h_kernel(const float* __restrict__ in, __half* __restrict__ out, int n4) {
    int i = blockIdx.x * blockDim.x + threadIdx.x;
    if (i < n4) {
        float4 v = ((const float4*)in)[i];
        __half2 h0 = __floats2half2_rn(v.x, v.y);
        __half2 h1 = __floats2half2_rn(v.z, v.w);
        uint2 u;
        u.x = *(uint32_t*)&h0; u.y = *(uint32_t*)&h1;
        ((uint2*)out)[i] = u;
    }
}

// ---------------- transpose + fp16 convert: in [R,C] fp32 -> out [C,R] fp16 ----------------
__global__ void transpose_h_kernel(const float* __restrict__ in, __half* __restrict__ out,
                                   int R, int C)
{
    __shared__ float t[32][33];
    int bx = blockIdx.x * 32, by = blockIdx.y * 32;
#pragma unroll
    for (int i = 0; i < 4; i++)
        t[threadIdx.y + 8 * i][threadIdx.x] =
            in[(size_t)(by + threadIdx.y + 8 * i) * C + bx + threadIdx.x];
    __syncthreads();
#pragma unroll
    for (int i = 0; i < 4; i++)
        out[(size_t)(bx + threadIdx.y + 8 * i) * R + by + threadIdx.x] =
            __float2half_rn(t[threadIdx.x][threadIdx.y + 8 * i]);
}

// ---------------- CSR build ----------------
__global__ void zero_counts_kernel() {
    int i = blockIdx.x * blockDim.x + threadIdx.x;
    if (i < NNODES) { g_deg[i] = 0; g_cur[i] = 0; }
}
__global__ void count_kernel(const int* __restrict__ dst) {
    int e = blockIdx.x * blockDim.x + threadIdx.x;
    if (e < NEDGES) atomicAdd(&g_deg[dst[e]], 1);
}
__global__ void scan_kernel() {
    __shared__ int s[1024];
    int t = threadIdx.x;
    int base = t * 8;
    int local[8];
    int run = 0;
#pragma unroll
    for (int i = 0; i < 8; i++) { local[i] = run; run += g_deg[base + i]; }
    s[t] = run;
    __syncthreads();
    for (int o = 1; o < 1024; o <<= 1) {
        int v = (t >= o) ? s[t - o] : 0;
        __syncthreads();
        s[t] += v;
        __syncthreads();
    }
    int prev = (t == 0) ? 0 : s[t - 1];
#pragma unroll
    for (int i = 0; i < 8; i++) g_off[base + i] = prev + local[i];
    if (t == 1023) g_off[NNODES] = s[1023];
}
__global__ void scatter_kernel(const int* __restrict__ dst) {
    int e = blockIdx.x * blockDim.x + threadIdx.x;
    if (e < NEDGES) {
        int d = dst[e];
        int p = atomicAdd(&g_cur[d], 1);
        g_eid[g_off[d] + p] = e;
    }
}

// ---------------- fp16 tensor-core GEMM ----------------
// C[M,N] = A[M,K] @ Bt^T ; A [M,K] half row-major, Bt [N,K] half row-major (K contig).
// Block 128x128x32, 8 warps (2x4), warp tile 64x32, double-buffered cp.async.
// smem row stride 40 halves -> conflict-free half2 fragment loads.
#define HSTR 40

__global__ void __launch_bounds__(256)
hgemm(const __half* __restrict__ A, const __half* __restrict__ Bt,
      float* __restrict__ C, int K, int N)
{
    __shared__ __half As[2][128 * HSTR];
    __shared__ __half Bs[2][128 * HSTR];

    const int tid = threadIdx.x, wid = tid >> 5, lane = tid & 31;
    const int bn = blockIdx.x, bm = blockIdx.y;
    const int wm = (wid >> 2) * 64;
    const int wn = (wid & 3) * 32;
    const int g = lane >> 2, tg = lane & 3;

    const __half* Ag = A + (size_t)(bm * 128) * K;
    const __half* Bg = Bt + (size_t)(bn * 128) * K;

    float acc[16][4] = {};
    const int T = K / 32;

    auto load_tile = [&](int t) {
        int buf = t & 1;
        int k0 = t * 32;
#pragma unroll
        for (int i = 0; i < 2; i++) {
            int ci = tid + i * 256;
            int r = ci >> 2, c = ci & 3;           // row 0..127, 16B-chunk 0..3
            cp16(smem_u32(&As[buf][r * HSTR + c * 8]), Ag + (size_t)r * K + k0 + c * 8);
            cp16(smem_u32(&Bs[buf][r * HSTR + c * 8]), Bg + (size_t)r * K + k0 + c * 8);
        }
        asm volatile("cp.async.commit_group;");
    };

    load_tile(0);

    for (int t = 0; t < T; t++) {
        asm volatile("cp.async.wait_group 0;");
        __syncthreads();
        if (t + 1 < T) load_tile(t + 1);

        const __half* Ab = As[t & 1];
        const __half* Bb = Bs[t & 1];
#pragma unroll
        for (int kc = 0; kc < 2; kc++) {
            uint32_t a[4][4], b[4][2];
#pragma unroll
            for (int mi = 0; mi < 4; mi++) {
                int base = (wm + mi * 16 + g) * HSTR + kc * 16 + 2 * tg;
                a[mi][0] = *(const uint32_t*)&Ab[base];
                a[mi][1] = *(const uint32_t*)&Ab[base + 8 * HSTR];
                a[mi][2] = *(const uint32_t*)&Ab[base + 8];
                a[mi][3] = *(const uint32_t*)&Ab[base + 8 * HSTR + 8];
            }
#pragma unroll
            for (int ni = 0; ni < 4; ni++) {
                int nb = (wn + ni * 8 + g) * HSTR + kc * 16 + 2 * tg;
                b[ni][0] = *(const uint32_t*)&Bb[nb];
                b[ni][1] = *(const uint32_t*)&Bb[nb + 8];
            }
#pragma unroll
            for (int mi = 0; mi < 4; mi++)
#pragma unroll
                for (int ni = 0; ni < 4; ni++)
                    MMA_F16(acc[mi * 4 + ni], a[mi], b[ni]);
        }
        __syncthreads();
    }

    // epilogue (same accumulator layout as m16n8k8: c0,c1=(g,2tg..), c2,c3=(g+8,..))
#pragma unroll
    for (int mi = 0; mi < 4; mi++) {
        int r0 = bm * 128 + wm + mi * 16 + g;
#pragma unroll
        for (int ni = 0; ni < 4; ni++) {
            int c = bn * 128 + wn + ni * 8 + tg * 2;
            float* p = C + (size_t)r0 * N + c;
            *(float2*)p = make_float2(acc[mi * 4 + ni][0], acc[mi * 4 + ni][1]);
            *(float2*)(p + (size_t)8 * N) = make_float2(acc[mi * 4 + ni][2], acc[mi * 4 + ni][3]);
        }
    }
}

// ---------------- per-(node,head) attention coefficients ----------------
__global__ void alphas_kernel(const float* __restrict__ h,
                              const float* __restrict__ a_s, const float* __restrict__ a_d,
                              float* __restrict__ out_s, float* __restrict__ out_d,
                              int H, int C)
{
    int w = (blockIdx.x * blockDim.x + threadIdx.x) >> 5;
    int lane = threadIdx.x & 31;
    if (w >= NNODES * H) return;
    int n = w / H, hd = w % H;
    const float* hp  = h + (size_t)n * H * C + (size_t)hd * C;
    const float* asp = a_s + (size_t)hd * C;
    const float* adp = a_d + (size_t)hd * C;
    float ss = 0.f, sd = 0.f;
    for (int c = lane; c < C; c += 32) {
        float v = hp[c];
        ss += v * asp[c];
        sd += v * adp[c];
    }
#pragma unroll
    for (int o = 16; o; o >>= 1) {
        ss += __shfl_down_sync(0xffffffffu, ss, o);
        sd += __shfl_down_sync(0xffffffffu, sd, o);
    }
    if (lane == 0) { out_s[w] = ss; out_d[w] = sd; }
}

// ---------------- per-(dst,head) segment softmax ----------------
__global__ void softmax_kernel(const int* __restrict__ src,
                               const float* __restrict__ as, const float* __restrict__ ad,
                               float* __restrict__ alpha, int H)
{
    int idx = blockIdx.x * blockDim.x + threadIdx.x;
    if (idx >= NNODES * H) return;
    int d = idx / H, hd = idx % H;
    int s0 = g_off[d], s1 = g_off[d + 1];
    if (s0 == s1) return;
    float adv = ad[idx];

    float m = -1e30f;
    for (int i = s0; i < s1; i++) {
        int e = g_eid[i];
        float x = as[src[e] * H + hd] + adv;
        x = (x > 0.f) ? x : NEG_SLOPE * x;
        m = fmaxf(m, x);
    }
    float sum = 0.f;
    for (int i = s0; i < s1; i++) {
        int e = g_eid[i];
        float x = as[src[e] * H + hd] + adv;
        x = (x > 0.f) ? x : NEG_SLOPE * x;
        float w = __expf(x - m);
        alpha[(size_t)e * H + hd] = w;
        sum += w;
    }
    float inv = 1.f / (sum + EPSV);
    for (int i = s0; i < s1; i++) {
        int e = g_eid[i];
        alpha[(size_t)e * H + hd] *= inv;
    }
}

// ---------------- aggregation ----------------
// acc = sum_e alpha * h[src] + b; layer1 (do_elu): out_h = fp16(elu(acc)); layer2: out_f = acc.
__global__ void __launch_bounds__(192)
aggregate_kernel(const int* __restrict__ src, const float* __restrict__ alpha,
                 const float* __restrict__ h, float* __restrict__ out_f,
                 __half* __restrict__ out_h, const float* __restrict__ bias,
                 int H, int C, int do_elu)
{
    int d  = blockIdx.x / H;
    int hd = blockIdx.x % H;
    int t  = threadIdx.x;
    int s0 = g_off[d], s1 = g_off[d + 1];
    size_t rs = (size_t)H * C;

    float4 acc = make_float4(0.f, 0.f, 0.f, 0.f);
    for (int i = s0; i < s1; i++) {
        int e = g_eid[i];
        float a = alpha[(size_t)e * H + hd];
        float4 v = *(((const float4*)(h + (size_t)src[e] * rs + (size_t)hd * C)) + t);
        acc.x += a * v.x; acc.y += a * v.y; acc.z += a * v.z; acc.w += a * v.w;
    }
    float4 b = *(((const float4*)(bias + (size_t)hd * C)) + t);
    acc.x += b.x; acc.y += b.y; acc.z += b.z; acc.w += b.w;
    if (do_elu) {
        acc.x = (acc.x > 0.f) ? acc.x : expm1f(acc.x);
        acc.y = (acc.y > 0.f) ? acc.y : expm1f(acc.y);
        acc.z = (acc.z > 0.f) ? acc.z : expm1f(acc.z);
        acc.w = (acc.w > 0.f) ? acc.w : expm1f(acc.w);
        __half2 h0 = __floats2half2_rn(acc.x, acc.y);
        __half2 h1 = __floats2half2_rn(acc.z, acc.w);
        uint2 u; u.x = *(uint32_t*)&h0; u.y = *(uint32_t*)&h1;
        *(((uint2*)(out_h + (size_t)d * rs + (size_t)hd * C)) + t) = u;
    } else {
        *(((float4*)(out_f + (size_t)d * rs + (size_t)hd * C)) + t) = acc;
    }
}

// ---------------- launch ----------------
extern "C" void kernel_launch(void* const* d_in, const int* in_sizes, int n_in,
                              void* d_out, int out_size)
{
    const float* x    = (const float*)d_in[0];
    const float* W1   = (const float*)d_in[1];
    const float* a_s1 = (const float*)d_in[2];
    const float* a_d1 = (const float*)d_in[3];
    const float* b1   = (const float*)d_in[4];
    const float* W2   = (const float*)d_in[5];
    const float* a_s2 = (const float*)d_in[6];
    const float* a_d2 = (const float*)d_in[7];
    const float* b2   = (const float*)d_in[8];
    const int* edges  = (const int*)d_in[9];
    const int* src = edges;
    const int* dst = edges + NEDGES;
    float* out = (float*)d_out;

    float *h1, *h2, *as1, *ad1, *as2, *ad2, *al1, *al2;
    __half *xh, *o1h, *w1th, *w2th;
    cudaGetSymbolAddress((void**)&h1,   g_h1);
    cudaGetSymbolAddress((void**)&h2,   g_h2);
    cudaGetSymbolAddress((void**)&xh,   g_xh);
    cudaGetSymbolAddress((void**)&o1h,  g_o1h);
    cudaGetSymbolAddress((void**)&w1th, g_w1th);
    cudaGetSymbolAddress((void**)&w2th, g_w2th);
    cudaGetSymbolAddress((void**)&as1,  g_as1);
    cudaGetSymbolAddress((void**)&ad1,  g_ad1);
    cudaGetSymbolAddress((void**)&as2,  g_as2);
    cudaGetSymbolAddress((void**)&ad2,  g_ad2);
    cudaGetSymbolAddress((void**)&al1,  g_alpha1);
    cudaGetSymbolAddress((void**)&al2,  g_alpha2);

    dim3 tblk(32, 8);

    // 0: x -> fp16
    f2h_kernel<<<(NNODES * DIN / 4 + 255) / 256, 256>>>(x, xh, NNODES * DIN / 4);
    // 1: W1 [768,6144] -> W1^T fp16 [6144,768]
    {
        dim3 gt((H1N * DHID) / 32, DIN / 32);
        transpose_h_kernel<<<gt, tblk>>>(W1, w1th, DIN, H1N * DHID);
    }
    // 2: W2 [6144,768] -> W2^T fp16 [768,6144]
    {
        dim3 gt(DHID / 32, (H1N * DHID) / 32);
        transpose_h_kernel<<<gt, tblk>>>(W2, w2th, H1N * DHID, DHID);
    }
    // 3: GEMM1 (ncu capture slot)  h1 = x @ W1  [8192, 6144]
    {
        dim3 grid((H1N * DHID) / 128, NNODES / 128);   // (48, 64)
        hgemm<<<grid, 256>>>(xh, w1th, h1, DIN, H1N * DHID);
    }
    // CSR build
    zero_counts_kernel<<<(NNODES + 255) / 256, 256>>>();
    count_kernel<<<(NEDGES + 255) / 256, 256>>>(dst);
    scan_kernel<<<1, 1024>>>();
    scatter_kernel<<<(NEDGES + 255) / 256, 256>>>(dst);
    // layer-1 attention + aggregation (writes o1 as fp16)
    alphas_kernel<<<(NNODES * H1N * 32 + 255) / 256, 256>>>(h1, a_s1, a_d1, as1, ad1, H1N, DHID);
    softmax_kernel<<<(NNODES * H1N + 255) / 256, 256>>>(src, as1, ad1, al1, H1N);
    aggregate_kernel<<<NNODES * H1N, DHID / 4>>>(src, al1, h1, nullptr, o1h, b1, H1N, DHID, 1);
    // GEMM2  h2 = o1 @ W2  [8192, 768]
    {
        dim3 grid((H2N * DHID) / 128, NNODES / 128);   // (6, 64)
        hgemm<<<grid, 256>>>(o1h, w2th, h2, H1N * DHID, H2N * DHID);
    }
    // layer-2 attention + aggregation (fp32 out)
    alphas_kernel<<<(NNODES * H2N * 32 + 255) / 256, 256>>>(h2, a_s2, a_d2, as2, ad2, H2N, DHID);
    softmax_kernel<<<(NNODES * H2N + 255) / 256, 256>>>(src, as2, ad2, al2, H2N);
    aggregate_kernel<<<NNODES * H2N, DHID / 4>>>(src, al2, h2, out, nullptr, b2, H2N, DHID, 0);
}